// round 4
// baseline (speedup 1.0000x reference)
#include <cuda_runtime.h>
#include <math.h>
#include <stddef.h>
#include <stdint.h>

#define SEQ    2048
#define DIMM   2048
#define HEADS  16
#define DHEAD  128
#define QKVN   2304
#define EPSF   1e-5f
#define MASKVF 1e-10f
#define SCALEF 0.08838834764831845f

// ---------------- scratch ---------------------------------------------------
__device__ float g_xn[SEQ * DIMM];
__device__ float g_wcatT[QKVN * DIMM];
__device__ float g_woT[DIMM * DIMM];
__device__ float g_qkv[SEQ * QKVN];
__device__ float g_ao[SEQ * DIMM];
__device__ float g_vsuf[SEQ * DHEAD];
__device__ float g_vpart[16 * DHEAD];
// attention operand planes
__device__ float g_qh[SEQ * DIMM];      // Q hi, fragment-packed
__device__ float g_ql[SEQ * DIMM];      // Q lo, fragment-packed
__device__ float g_kh[SEQ * DHEAD];
__device__ float g_kl[SEQ * DHEAD];
__device__ float g_vh[SEQ * DHEAD];
__device__ float g_vl[SEQ * DHEAD];

// ---------------- helpers ----------------------------------------------------
__device__ __forceinline__ float to_tf32(float x) {
    float r; asm("cvt.rna.tf32.f32 %0, %1;" : "=f"(r) : "f"(x)); return r;
}
__device__ __forceinline__ void cvt_hl(float x, float& h, float& l) {
    h = to_tf32(x); l = to_tf32(x - h);
}
#define MMA_TF32(Cacc, Av, Bv)                                              \
    asm volatile("mma.sync.aligned.m16n8k8.row.col.f32.tf32.tf32.f32 "      \
        "{%0,%1,%2,%3}, {%4,%5,%6,%7}, {%8,%9}, {%0,%1,%2,%3};"             \
        : "+f"((Cacc)[0]), "+f"((Cacc)[1]), "+f"((Cacc)[2]), "+f"((Cacc)[3])\
        : "r"((Av).x), "r"((Av).y), "r"((Av).z), "r"((Av).w),               \
          "r"((Bv).x), "r"((Bv).y))

// ---------------- RMSNorm ---------------------------------------------------
__global__ void rmsnorm_kernel(const float* __restrict__ x,
                               const float* __restrict__ gamma) {
    int row = blockIdx.x;
    const float* xr = x + (size_t)row * DIMM;
    float ss = 0.f;
    for (int i = threadIdx.x; i < DIMM; i += 256) { float v = xr[i]; ss += v * v; }
    __shared__ float red[8];
    #pragma unroll
    for (int o = 16; o; o >>= 1) ss += __shfl_xor_sync(0xffffffffu, ss, o);
    if ((threadIdx.x & 31) == 0) red[threadIdx.x >> 5] = ss;
    __syncthreads();
    if (threadIdx.x < 32) {
        float v = (threadIdx.x < 8) ? red[threadIdx.x] : 0.f;
        #pragma unroll
        for (int o = 4; o; o >>= 1) v += __shfl_xor_sync(0xffffffffu, v, o);
        if (threadIdx.x == 0) red[0] = v;
    }
    __syncthreads();
    float inv = rsqrtf(red[0] / (float)DIMM + EPSF);
    for (int i = threadIdx.x; i < DIMM; i += 256)
        g_xn[(size_t)row * DIMM + i] = xr[i] * inv * gamma[i];
}

// ---------------- tiled transpose -------------------------------------------
__global__ void transpose_kernel(const float* __restrict__ src, float* __restrict__ dst,
                                 int R, int C, float scale) {
    __shared__ float tile[32][33];
    int bx = blockIdx.x * 32, by = blockIdx.y * 32;
    int tx = threadIdx.x, ty = threadIdx.y;
    #pragma unroll
    for (int j = 0; j < 32; j += 8)
        tile[ty + j][tx] = src[(size_t)(by + ty + j) * C + bx + tx];
    __syncthreads();
    #pragma unroll
    for (int j = 0; j < 32; j += 8)
        dst[(size_t)(bx + ty + j) * R + by + tx] = tile[tx][ty + j] * scale;
}

// ---------------- mma.sync tf32x3 GEMM (validated in R3) ---------------------
__global__ __launch_bounds__(256) void mma_gemm_kernel(
    const float* __restrict__ A, const float* __restrict__ Bt,
    float* __restrict__ C, int M, int N, int K)
{
    extern __shared__ float sm[];
    const int tid = threadIdx.x, lane = tid & 31, warp = tid >> 5;
    const int m0 = blockIdx.y << 7, n0 = blockIdx.x << 7;
    const int wm = warp >> 1, wn = warp & 1;
    const int gid = lane >> 2, tig = lane & 3;

    float acc[2][8][4];
    #pragma unroll
    for (int mf = 0; mf < 2; mf++)
        #pragma unroll
        for (int nf = 0; nf < 8; nf++)
            #pragma unroll
            for (int q = 0; q < 4; q++) acc[mf][nf][q] = 0.f;

    float rA[4][4], rB[8][2];
    #pragma unroll
    for (int i = 0; i < 4; i++) {
        int slot = warp + 8 * i, g = slot >> 2, k8 = slot & 3;
        const float* p = A + (size_t)(m0 + g * 16 + gid) * K + k8 * 8 + tig;
        rA[i][0] = p[0]; rA[i][1] = p[(size_t)8 * K];
        rA[i][2] = p[4]; rA[i][3] = p[(size_t)8 * K + 4];
    }
    #pragma unroll
    for (int j = 0; j < 8; j++) {
        int slot = warp + 8 * j, gg = slot >> 2, k8 = slot & 3;
        const float* p = Bt + (size_t)(n0 + gg * 8 + gid) * K + k8 * 8 + tig;
        rB[j][0] = p[0]; rB[j][1] = p[4];
    }

    const int S = K >> 5;
    for (int s = 0; s < S; s++) {
        float* buf = sm + (s & 1) * 16384;
        #pragma unroll
        for (int i = 0; i < 4; i++) {
            int slot = warp + 8 * i;
            float4 h, l;
            cvt_hl(rA[i][0], h.x, l.x); cvt_hl(rA[i][1], h.y, l.y);
            cvt_hl(rA[i][2], h.z, l.z); cvt_hl(rA[i][3], h.w, l.w);
            *(float4*)(buf + slot * 128 + lane * 4) = h;
            *(float4*)(buf + 4096 + slot * 128 + lane * 4) = l;
        }
        #pragma unroll
        for (int j = 0; j < 8; j++) {
            int slot = warp + 8 * j;
            float2 h, l;
            cvt_hl(rB[j][0], h.x, l.x); cvt_hl(rB[j][1], h.y, l.y);
            *(float2*)(buf + 8192 + slot * 64 + lane * 2) = h;
            *(float2*)(buf + 12288 + slot * 64 + lane * 2) = l;
        }
        __syncthreads();

        if (s + 1 < S) {
            const int k0 = (s + 1) << 5;
            #pragma unroll
            for (int i = 0; i < 4; i++) {
                int slot = warp + 8 * i, g = slot >> 2, k8 = slot & 3;
                const float* p = A + (size_t)(m0 + g * 16 + gid) * K + k0 + k8 * 8 + tig;
                rA[i][0] = p[0]; rA[i][1] = p[(size_t)8 * K];
                rA[i][2] = p[4]; rA[i][3] = p[(size_t)8 * K + 4];
            }
            #pragma unroll
            for (int j = 0; j < 8; j++) {
                int slot = warp + 8 * j, gg = slot >> 2, k8 = slot & 3;
                const float* p = Bt + (size_t)(n0 + gg * 8 + gid) * K + k0 + k8 * 8 + tig;
                rB[j][0] = p[0]; rB[j][1] = p[4];
            }
        }

        const uint4* Ah4 = (const uint4*)(buf);
        const uint4* Al4 = (const uint4*)(buf + 4096);
        const uint2* Bh2 = (const uint2*)(buf + 8192);
        const uint2* Bl2 = (const uint2*)(buf + 12288);
        #pragma unroll
        for (int k8 = 0; k8 < 4; k8++) {
            uint4 ah[2], al[2];
            #pragma unroll
            for (int mf = 0; mf < 2; mf++) {
                int slot = (wm * 2 + mf) * 4 + k8;
                ah[mf] = Ah4[slot * 32 + lane];
                al[mf] = Al4[slot * 32 + lane];
            }
            #pragma unroll
            for (int nf = 0; nf < 8; nf++) {
                int slot = (wn * 8 + nf) * 4 + k8;
                uint2 bh = Bh2[slot * 32 + lane];
                uint2 bl = Bl2[slot * 32 + lane];
                #pragma unroll
                for (int mf = 0; mf < 2; mf++) {
                    MMA_TF32(acc[mf][nf], ah[mf], bh);
                    MMA_TF32(acc[mf][nf], ah[mf], bl);
                    MMA_TF32(acc[mf][nf], al[mf], bh);
                }
            }
        }
        __syncthreads();
    }

    #pragma unroll
    for (int mf = 0; mf < 2; mf++) {
        const int r0 = m0 + wm * 32 + mf * 16 + gid;
        #pragma unroll
        for (int nf = 0; nf < 8; nf++) {
            const int c = n0 + wn * 64 + nf * 8 + tig * 2;
            float2 v0, v1;
            v0.x = acc[mf][nf][0]; v0.y = acc[mf][nf][1];
            v1.x = acc[mf][nf][2]; v1.y = acc[mf][nf][3];
            *(float2*)(C + (size_t)r0 * N + c) = v0;
            *(float2*)(C + (size_t)(r0 + 8) * N + c) = v1;
        }
    }
}

// ---------------- prep: Q fragment-packed hi/lo planes ------------------------
// out index: ((kk*128 + rg)*32 + lane)*4 + {a0,a1,a2,a3}
__global__ void qfrag_prep_kernel() {
    int t = blockIdx.x * 256 + threadIdx.x;     // 1,048,576 total
    int lane = t & 31;
    int rg = (t >> 5) & 127;
    int kk = t >> 12;
    int gid = lane >> 2, tig = lane & 3;
    int r0 = rg * 16 + gid, c0 = kk * 8 + tig;
    float a0 = g_qkv[(size_t)r0 * QKVN + c0];
    float a1 = g_qkv[(size_t)(r0 + 8) * QKVN + c0];
    float a2 = g_qkv[(size_t)r0 * QKVN + c0 + 4];
    float a3 = g_qkv[(size_t)(r0 + 8) * QKVN + c0 + 4];
    float4 h, l;
    cvt_hl(a0, h.x, l.x); cvt_hl(a1, h.y, l.y);
    cvt_hl(a2, h.z, l.z); cvt_hl(a3, h.w, l.w);
    *(float4*)(g_qh + (size_t)t * 4) = h;
    *(float4*)(g_ql + (size_t)t * 4) = l;
}

// ---------------- prep: K/V hi/lo planes (row-major) ---------------------------
__global__ void kv_prep_kernel() {
    int t = blockIdx.x * 256 + threadIdx.x;     // 65536 total
    int row = t >> 5, c4 = (t & 31) * 4;
    float4 k = *(const float4*)&g_qkv[(size_t)row * QKVN + DIMM + c4];
    float4 v = *(const float4*)&g_qkv[(size_t)row * QKVN + DIMM + DHEAD + c4];
    float4 kh, kl, vh, vl;
    cvt_hl(k.x, kh.x, kl.x); cvt_hl(k.y, kh.y, kl.y);
    cvt_hl(k.z, kh.z, kl.z); cvt_hl(k.w, kh.w, kl.w);
    cvt_hl(v.x, vh.x, vl.x); cvt_hl(v.y, vh.y, vl.y);
    cvt_hl(v.z, vh.z, vl.z); cvt_hl(v.w, vh.w, vl.w);
    *(float4*)&g_kh[(size_t)row * DHEAD + c4] = kh;
    *(float4*)&g_kl[(size_t)row * DHEAD + c4] = kl;
    *(float4*)&g_vh[(size_t)row * DHEAD + c4] = vh;
    *(float4*)&g_vl[(size_t)row * DHEAD + c4] = vl;
}

// ---------------- V suffix sums ------------------------------------------------
__global__ void vpart_kernel() {
    int blk = blockIdx.x, d = threadIdx.x;
    float s = 0.f;
    #pragma unroll 8
    for (int r = 0; r < 128; r++)
        s += g_qkv[(size_t)(blk * 128 + r) * QKVN + DIMM + DHEAD + d];
    g_vpart[blk * DHEAD + d] = s;
}
__global__ void vsuf_kernel() {
    int blk = blockIdx.x, d = threadIdx.x;
    float acc = 0.f;
    for (int b = blk + 1; b < 16; b++) acc += g_vpart[b * DHEAD + d];
    #pragma unroll 4
    for (int r = 127; r >= 0; r--) {
        int row = blk * 128 + r;
        g_vsuf[(size_t)row * DHEAD + d] = acc;
        acc += g_qkv[(size_t)row * QKVN + DIMM + DHEAD + d];
    }
}

// ---------------- tensor-core flash attention ---------------------------------
// CTA: 64 q-rows, j-steps of 64. 8 warps = 4 row-groups (wm) x 2 halves (wn).
// smem float offsets:
//   Kth[128][68] @0, Ktl @8704, Vsh[64][132] @17408, Vsl @25856,
//   Ph[64][68] @34304, Pl @38656, srmax[2][64] @43008, srsum[2][64] @43136
__global__ __launch_bounds__(256) void attn_mma_kernel(const float* __restrict__ pos_bias) {
    extern __shared__ float sm[];
    float* Kth = sm;
    float* Ktl = sm + 8704;
    float* Vsh = sm + 17408;
    float* Vsl = sm + 25856;
    float* Ph  = sm + 34304;
    float* Pl  = sm + 38656;
    float* srmax = sm + 43008;
    float* srsum = sm + 43136;

    const int h  = blockIdx.y;
    const int ib = gridDim.x - 1 - blockIdx.x;
    const int i0 = ib * 64;
    const int tid = threadIdx.x, lane = tid & 31, warp = tid >> 5;
    const int wm = warp >> 1, wn = warp & 1;
    const int gid = lane >> 2, tig = lane & 3;

    const int rg = (i0 >> 4) + wm;
    const size_t qoff = (size_t)(h * 16) * 16384 + (size_t)rg * 128 + lane * 4;

    const int jload = tid & 63, cb = tid >> 6;   // K loader
    const int r0g = i0 + wm * 16 + gid, r1g = r0g + 8;
    const int rl0 = wm * 16 + gid;               // local row

    float o[8][4];
    #pragma unroll
    for (int nf = 0; nf < 8; nf++)
        #pragma unroll
        for (int q = 0; q < 4; q++) o[nf][q] = 0.f;
    float m0 = -1e30f, m1 = -1e30f, l0 = 0.f, l1 = 0.f;

    for (int jb = 0; jb <= ib; jb++) {
        const int j0 = jb * 64;
        __syncthreads();
        // ---- V tile: [j][d] pad 132, hi/lo
        #pragma unroll
        for (int it = 0; it < 8; it++) {
            int row = warp + it * 8;
            size_t src = (size_t)(j0 + row) * DHEAD + lane * 4;
            *(float4*)&Vsh[row * 132 + lane * 4] = *(const float4*)&g_vh[src];
            *(float4*)&Vsl[row * 132 + lane * 4] = *(const float4*)&g_vl[src];
        }
        // ---- K tile transposed: Kt[d][j] pad 68, hi/lo
        #pragma unroll
        for (int it = 0; it < 8; it++) {
            int d4 = (it * 4 + cb) * 4;
            float4 kh = *(const float4*)&g_kh[(size_t)(j0 + jload) * DHEAD + d4];
            float4 kl = *(const float4*)&g_kl[(size_t)(j0 + jload) * DHEAD + d4];
            Kth[(d4 + 0) * 68 + jload] = kh.x; Kth[(d4 + 1) * 68 + jload] = kh.y;
            Kth[(d4 + 2) * 68 + jload] = kh.z; Kth[(d4 + 3) * 68 + jload] = kh.w;
            Ktl[(d4 + 0) * 68 + jload] = kl.x; Ktl[(d4 + 1) * 68 + jload] = kl.y;
            Ktl[(d4 + 2) * 68 + jload] = kl.z; Ktl[(d4 + 3) * 68 + jload] = kl.w;
        }
        __syncthreads();

        // ---- S = Q K^T  (tf32 x3)
        float s[4][4];
        #pragma unroll
        for (int nf = 0; nf < 4; nf++)
            #pragma unroll
            for (int q = 0; q < 4; q++) s[nf][q] = 0.f;

        #pragma unroll
        for (int k8 = 0; k8 < 16; k8++) {
            uint4 qh = *(const uint4*)(g_qh + qoff + (size_t)k8 * 16384);
            uint4 ql = *(const uint4*)(g_ql + qoff + (size_t)k8 * 16384);
            const int kr0 = (k8 * 8 + tig) * 68, kr1 = kr0 + 4 * 68;
            #pragma unroll
            for (int nf = 0; nf < 4; nf++) {
                int col = wn * 32 + nf * 8 + gid;
                uint2 bh = make_uint2(__float_as_uint(Kth[kr0 + col]),
                                      __float_as_uint(Kth[kr1 + col]));
                uint2 bl = make_uint2(__float_as_uint(Ktl[kr0 + col]),
                                      __float_as_uint(Ktl[kr1 + col]));
                MMA_TF32(s[nf], qh, bh);
                MMA_TF32(s[nf], qh, bl);
                MMA_TF32(s[nf], ql, bh);
            }
        }

        // ---- + pos_bias, causal mask (diagonal block only)
        const float* pb0 = pos_bias + ((size_t)h * SEQ + r0g) * SEQ + j0 + wn * 32 + tig * 2;
        const float* pb1 = pb0 + (size_t)8 * SEQ;
        #pragma unroll
        for (int nf = 0; nf < 4; nf++) {
            float2 b0 = *(const float2*)(pb0 + nf * 8);
            float2 b1 = *(const float2*)(pb1 + nf * 8);
            s[nf][0] += b0.x; s[nf][1] += b0.y;
            s[nf][2] += b1.x; s[nf][3] += b1.y;
        }
        if (jb == ib) {
            #pragma unroll
            for (int nf = 0; nf < 4; nf++) {
                int c = j0 + wn * 32 + nf * 8 + tig * 2;
                if (c > r0g)     s[nf][0] = -1e30f;
                if (c + 1 > r0g) s[nf][1] = -1e30f;
                if (c > r1g)     s[nf][2] = -1e30f;
                if (c + 1 > r1g) s[nf][3] = -1e30f;
            }
        }

        // ---- row max (quad shuffle + cross-half smem)
        float rm0 = -1e30f, rm1 = -1e30f;
        #pragma unroll
        for (int nf = 0; nf < 4; nf++) {
            rm0 = fmaxf(rm0, fmaxf(s[nf][0], s[nf][1]));
            rm1 = fmaxf(rm1, fmaxf(s[nf][2], s[nf][3]));
        }
        rm0 = fmaxf(rm0, __shfl_xor_sync(0xffffffffu, rm0, 1));
        rm0 = fmaxf(rm0, __shfl_xor_sync(0xffffffffu, rm0, 2));
        rm1 = fmaxf(rm1, __shfl_xor_sync(0xffffffffu, rm1, 1));
        rm1 = fmaxf(rm1, __shfl_xor_sync(0xffffffffu, rm1, 2));
        srmax[wn * 64 + rl0] = rm0;
        srmax[wn * 64 + rl0 + 8] = rm1;
        __syncthreads();
        float bm0 = fmaxf(srmax[rl0], srmax[64 + rl0]);
        float bm1 = fmaxf(srmax[rl0 + 8], srmax[64 + rl0 + 8]);
        float mn0 = fmaxf(m0, bm0), mn1 = fmaxf(m1, bm1);
        float sc0 = __expf(m0 - mn0), sc1 = __expf(m1 - mn1);

        // ---- exp + P staging (hi/lo) + row sum
        float rs0 = 0.f, rs1 = 0.f;
        #pragma unroll
        for (int nf = 0; nf < 4; nf++) {
            int col = wn * 32 + nf * 8 + tig * 2;
            float p00 = __expf(s[nf][0] - mn0);
            float p01 = __expf(s[nf][1] - mn0);
            float p10 = __expf(s[nf][2] - mn1);
            float p11 = __expf(s[nf][3] - mn1);
            rs0 += p00 + p01; rs1 += p10 + p11;
            float hh, ll;
            cvt_hl(p00, hh, ll); Ph[rl0 * 68 + col] = hh;       Pl[rl0 * 68 + col] = ll;
            cvt_hl(p01, hh, ll); Ph[rl0 * 68 + col + 1] = hh;   Pl[rl0 * 68 + col + 1] = ll;
            cvt_hl(p10, hh, ll); Ph[(rl0 + 8) * 68 + col] = hh; Pl[(rl0 + 8) * 68 + col] = ll;
            cvt_hl(p11, hh, ll); Ph[(rl0 + 8) * 68 + col + 1] = hh; Pl[(rl0 + 8) * 68 + col + 1] = ll;
        }
        rs0 += __shfl_xor_sync(0xffffffffu, rs0, 1);
        rs0 += __shfl_xor_sync(0xffffffffu, rs0, 2);
        rs1 += __shfl_xor_sync(0xffffffffu, rs1, 1);
        rs1 += __shfl_xor_sync(0xffffffffu, rs1, 2);
        srsum[wn * 64 + rl0] = rs0;
        srsum[wn * 64 + rl0 + 8] = rs1;
        __syncthreads();
        l0 = l0 * sc0 + srsum[rl0] + srsum[64 + rl0];
        l1 = l1 * sc1 + srsum[rl0 + 8] + srsum[64 + rl0 + 8];
        m0 = mn0; m1 = mn1;

        // ---- rescale O, then O += P V (tf32 x3)
        #pragma unroll
        for (int nf = 0; nf < 8; nf++) {
            o[nf][0] *= sc0; o[nf][1] *= sc0;
            o[nf][2] *= sc1; o[nf][3] *= sc1;
        }
        #pragma unroll
        for (int k8 = 0; k8 < 8; k8++) {
            const int pc0 = k8 * 8 + tig, pc1 = pc0 + 4;
            uint4 ah = make_uint4(__float_as_uint(Ph[rl0 * 68 + pc0]),
                                  __float_as_uint(Ph[(rl0 + 8) * 68 + pc0]),
                                  __float_as_uint(Ph[rl0 * 68 + pc1]),
                                  __float_as_uint(Ph[(rl0 + 8) * 68 + pc1]));
            uint4 al = make_uint4(__float_as_uint(Pl[rl0 * 68 + pc0]),
                                  __float_as_uint(Pl[(rl0 + 8) * 68 + pc0]),
                                  __float_as_uint(Pl[rl0 * 68 + pc1]),
                                  __float_as_uint(Pl[(rl0 + 8) * 68 + pc1]));
            const int vr0 = (k8 * 8 + tig) * 132, vr1 = vr0 + 4 * 132;
            #pragma unroll
            for (int nf = 0; nf < 8; nf++) {
                int dcol = wn * 64 + nf * 8 + gid;
                uint2 bh = make_uint2(__float_as_uint(Vsh[vr0 + dcol]),
                                      __float_as_uint(Vsh[vr1 + dcol]));
                uint2 bl = make_uint2(__float_as_uint(Vsl[vr0 + dcol]),
                                      __float_as_uint(Vsl[vr1 + dcol]));
                MMA_TF32(o[nf], ah, bh);
                MMA_TF32(o[nf], ah, bl);
                MMA_TF32(o[nf], al, bh);
            }
        }
    }

    // ---- finalize with analytic MASK_VALUE tail
    float cnt0 = (float)(SEQ - 1 - r0g), cnt1 = (float)(SEQ - 1 - r1g);
    float mf0 = fmaxf(m0, MASKVF), mf1 = fmaxf(m1, MASKVF);
    float wu0 = __expf(m0 - mf0),  wu1 = __expf(m1 - mf1);
    float wk0 = __expf(MASKVF - mf0), wk1 = __expf(MASKVF - mf1);
    float iZ0 = 1.f / (l0 * wu0 + cnt0 * wk0);
    float iZ1 = 1.f / (l1 * wu1 + cnt1 * wk1);
    #pragma unroll
    for (int nf = 0; nf < 8; nf++) {
        int dcol = wn * 64 + nf * 8 + tig * 2;
        float2 vs0 = *(const float2*)&g_vsuf[(size_t)r0g * DHEAD + dcol];
        float2 vs1 = *(const float2*)&g_vsuf[(size_t)r1g * DHEAD + dcol];
        float2 out0, out1;
        out0.x = (o[nf][0] * wu0 + wk0 * vs0.x) * iZ0;
        out0.y = (o[nf][1] * wu0 + wk0 * vs0.y) * iZ0;
        out1.x = (o[nf][2] * wu1 + wk1 * vs1.x) * iZ1;
        out1.y = (o[nf][3] * wu1 + wk1 * vs1.y) * iZ1;
        *(float2*)&g_ao[(size_t)r0g * DIMM + h * DHEAD + dcol] = out0;
        *(float2*)&g_ao[(size_t)r1g * DIMM + h * DHEAD + dcol] = out1;
    }
}

// ---------------- launch ---------------------------------------------------------
extern "C" void kernel_launch(void* const* d_in, const int* in_sizes, int n_in,
                              void* d_out, int out_size) {
    (void)in_sizes; (void)n_in; (void)out_size;
    const float* x        = (const float*)d_in[0];
    const float* pos_bias = (const float*)d_in[1];
    const float* gamma    = (const float*)d_in[2];
    const float* wq       = (const float*)d_in[3];
    const float* wk       = (const float*)d_in[4];
    const float* wv       = (const float*)d_in[5];
    const float* wo       = (const float*)d_in[6];
    float* out = (float*)d_out;

    float *xn_p, *wcatT_p, *woT_p, *qkv_p, *ao_p;
    cudaGetSymbolAddress((void**)&xn_p,    g_xn);
    cudaGetSymbolAddress((void**)&wcatT_p, g_wcatT);
    cudaGetSymbolAddress((void**)&woT_p,   g_woT);
    cudaGetSymbolAddress((void**)&qkv_p,   g_qkv);
    cudaGetSymbolAddress((void**)&ao_p,    g_ao);

    const int MMA_SMEM  = 2 * 16384 * 4;     // 131072
    const int ATTN_SMEM = 43264 * 4;         // 173056
    cudaFuncSetAttribute(mma_gemm_kernel, cudaFuncAttributeMaxDynamicSharedMemorySize, MMA_SMEM);
    cudaFuncSetAttribute(attn_mma_kernel, cudaFuncAttributeMaxDynamicSharedMemorySize, ATTN_SMEM);

    dim3 tb(32, 8);
    transpose_kernel<<<dim3(DIMM / 32, DIMM / 32), tb>>>(wq, wcatT_p, DIMM, DIMM, SCALEF);
    transpose_kernel<<<dim3(DHEAD / 32, DIMM / 32), tb>>>(wk, wcatT_p + (size_t)2048 * DIMM, DIMM, DHEAD, 1.0f);
    transpose_kernel<<<dim3(DHEAD / 32, DIMM / 32), tb>>>(wv, wcatT_p + (size_t)2176 * DIMM, DIMM, DHEAD, 1.0f);
    transpose_kernel<<<dim3(DIMM / 32, DIMM / 32), tb>>>(wo, woT_p, DIMM, DIMM, 1.0f);

    rmsnorm_kernel<<<SEQ, 256>>>(x, gamma);

    mma_gemm_kernel<<<dim3(QKVN / 128, SEQ / 128), 256, MMA_SMEM>>>(
        xn_p, wcatT_p, qkv_p, SEQ, QKVN, DIMM);

    qfrag_prep_kernel<<<4096, 256>>>();
    kv_prep_kernel<<<256, 256>>>();
    vpart_kernel<<<16, 128>>>();
    vsuf_kernel<<<16, 128>>>();

    attn_mma_kernel<<<dim3(32, HEADS), 256, ATTN_SMEM>>>(pos_bias);

    mma_gemm_kernel<<<dim3(DIMM / 128, SEQ / 128), 256, MMA_SMEM>>>(
        ao_p, woT_p, out, SEQ, DIMM, DIMM);
}

// round 5
// speedup vs baseline: 1.9325x; 1.9325x over previous
#include <cuda_runtime.h>
#include <cuda_fp16.h>
#include <math.h>
#include <stddef.h>
#include <stdint.h>

#define SEQ    2048
#define DIMM   2048
#define HEADS  16
#define DHEAD  128
#define QKVN   2304
#define EPSF   1e-5f
#define MASKVF 1e-10f
#define SCALEF 0.08838834764831845f

// ---------------- scratch ---------------------------------------------------
__device__ float g_xn[SEQ * DIMM];
__device__ float g_wcatT[QKVN * DIMM];
__device__ float g_woT[DIMM * DIMM];
__device__ float g_qkv[SEQ * QKVN];
__device__ float g_ao[SEQ * DIMM];
__device__ float g_vsuf[SEQ * DHEAD];
__device__ float g_vpart[16 * DHEAD];
// fp16 hi/lo operand planes for attention
__device__ uint4    g_qh4[HEADS * 128 * 8 * 32];   // Q fragments, 8 MB
__device__ uint4    g_ql4[HEADS * 128 * 8 * 32];
__device__ unsigned g_kt2h[64 * SEQ];              // K^T, half2 packed along d
__device__ unsigned g_kt2l[64 * SEQ];
__device__ unsigned g_vt2h[(SEQ / 2) * DHEAD];     // V, half2 packed along j
__device__ unsigned g_vt2l[(SEQ / 2) * DHEAD];

// ---------------- helpers ----------------------------------------------------
__device__ __forceinline__ void cvt_h2(float x0, float x1, unsigned& h, unsigned& l) {
    __half2 hh = __floats2half2_rn(x0, x1);
    __half2 ll = __floats2half2_rn(x0 - __low2float(hh), x1 - __high2float(hh));
    h = *reinterpret_cast<unsigned*>(&hh);
    l = *reinterpret_cast<unsigned*>(&ll);
}
#define MMA_F16(Cacc, Av, Bv)                                               \
    asm volatile("mma.sync.aligned.m16n8k16.row.col.f32.f16.f16.f32 "       \
        "{%0,%1,%2,%3}, {%4,%5,%6,%7}, {%8,%9}, {%0,%1,%2,%3};"             \
        : "+f"((Cacc)[0]), "+f"((Cacc)[1]), "+f"((Cacc)[2]), "+f"((Cacc)[3])\
        : "r"((Av).x), "r"((Av).y), "r"((Av).z), "r"((Av).w),               \
          "r"((Bv).x), "r"((Bv).y))

// ---------------- RMSNorm ---------------------------------------------------
__global__ void rmsnorm_kernel(const float* __restrict__ x,
                               const float* __restrict__ gamma) {
    int row = blockIdx.x;
    const float* xr = x + (size_t)row * DIMM;
    float ss = 0.f;
    for (int i = threadIdx.x; i < DIMM; i += 256) { float v = xr[i]; ss += v * v; }
    __shared__ float red[8];
    #pragma unroll
    for (int o = 16; o; o >>= 1) ss += __shfl_xor_sync(0xffffffffu, ss, o);
    if ((threadIdx.x & 31) == 0) red[threadIdx.x >> 5] = ss;
    __syncthreads();
    if (threadIdx.x < 32) {
        float v = (threadIdx.x < 8) ? red[threadIdx.x] : 0.f;
        #pragma unroll
        for (int o = 4; o; o >>= 1) v += __shfl_xor_sync(0xffffffffu, v, o);
        if (threadIdx.x == 0) red[0] = v;
    }
    __syncthreads();
    float inv = rsqrtf(red[0] / (float)DIMM + EPSF);
    for (int i = threadIdx.x; i < DIMM; i += 256)
        g_xn[(size_t)row * DIMM + i] = xr[i] * inv * gamma[i];
}

// ---------------- tiled transpose -------------------------------------------
__global__ void transpose_kernel(const float* __restrict__ src, float* __restrict__ dst,
                                 int R, int C, float scale) {
    __shared__ float tile[32][33];
    int bx = blockIdx.x * 32, by = blockIdx.y * 32;
    int tx = threadIdx.x, ty = threadIdx.y;
    #pragma unroll
    for (int j = 0; j < 32; j += 8)
        tile[ty + j][tx] = src[(size_t)(by + ty + j) * C + bx + tx];
    __syncthreads();
    #pragma unroll
    for (int j = 0; j < 32; j += 8)
        dst[(size_t)(bx + ty + j) * R + by + tx] = tile[tx][ty + j] * scale;
}

// ---------------- mma.sync fp16x3 GEMM: C[M,N] = A[M,K] @ Bt[N,K]^T ----------
// 128x128 tile, 8 warps (4m x 2n), K-stage 32 (2 k16 chunks), double-buffered.
// Buffer (floats): Ah[16 slots][32]uint4 @0(2048), Al @2048, Bh[32][32]uint2
// @4096(2048), Bl @6144.  8192 floats = 32 KB per buffer.
__global__ __launch_bounds__(256) void mma_gemm_kernel(
    const float* __restrict__ A, const float* __restrict__ Bt,
    float* __restrict__ C, int M, int N, int K)
{
    extern __shared__ float sm[];
    const int tid = threadIdx.x, lane = tid & 31, warp = tid >> 5;
    const int m0 = blockIdx.y << 7, n0 = blockIdx.x << 7;
    const int wm = warp >> 1, wn = warp & 1;
    const int gid = lane >> 2, tig = lane & 3;

    float acc[2][8][4];
    #pragma unroll
    for (int mf = 0; mf < 2; mf++)
        #pragma unroll
        for (int nf = 0; nf < 8; nf++)
            #pragma unroll
            for (int q = 0; q < 4; q++) acc[mf][nf][q] = 0.f;

    float2 rA[2][4], rB[4][2];
    // prologue (kb = 0)
    #pragma unroll
    for (int i = 0; i < 2; i++) {
        const int row0 = m0 + warp * 16 + gid, c0 = i * 16 + tig * 2;
        rA[i][0] = *(const float2*)(A + (size_t)row0 * K + c0);
        rA[i][1] = *(const float2*)(A + (size_t)(row0 + 8) * K + c0);
        rA[i][2] = *(const float2*)(A + (size_t)row0 * K + c0 + 8);
        rA[i][3] = *(const float2*)(A + (size_t)(row0 + 8) * K + c0 + 8);
    }
    #pragma unroll
    for (int j = 0; j < 4; j++) {
        const int n = n0 + (warp + 8 * (j & 1)) * 8 + gid, k0 = (j >> 1) * 16 + tig * 2;
        rB[j][0] = *(const float2*)(Bt + (size_t)n * K + k0);
        rB[j][1] = *(const float2*)(Bt + (size_t)n * K + k0 + 8);
    }

    const int S = K >> 5;
    for (int s = 0; s < S; s++) {
        float* buf = sm + (s & 1) * 8192;
        uint4* Ah4 = (uint4*)buf;
        uint4* Al4 = (uint4*)(buf + 2048);
        uint2* Bh2 = (uint2*)(buf + 4096);
        uint2* Bl2 = (uint2*)(buf + 6144);

        #pragma unroll
        for (int i = 0; i < 2; i++) {
            int slot = warp + 8 * i;
            uint4 hv, lv;
            cvt_h2(rA[i][0].x, rA[i][0].y, hv.x, lv.x);
            cvt_h2(rA[i][1].x, rA[i][1].y, hv.y, lv.y);
            cvt_h2(rA[i][2].x, rA[i][2].y, hv.z, lv.z);
            cvt_h2(rA[i][3].x, rA[i][3].y, hv.w, lv.w);
            Ah4[slot * 32 + lane] = hv;
            Al4[slot * 32 + lane] = lv;
        }
        #pragma unroll
        for (int j = 0; j < 4; j++) {
            int slot = (j >> 1) * 16 + warp + 8 * (j & 1);
            uint2 hv, lv;
            cvt_h2(rB[j][0].x, rB[j][0].y, hv.x, lv.x);
            cvt_h2(rB[j][1].x, rB[j][1].y, hv.y, lv.y);
            Bh2[slot * 32 + lane] = hv;
            Bl2[slot * 32 + lane] = lv;
        }
        __syncthreads();

        if (s + 1 < S) {
            const int kb = (s + 1) << 5;
            #pragma unroll
            for (int i = 0; i < 2; i++) {
                const int row0 = m0 + warp * 16 + gid, c0 = kb + i * 16 + tig * 2;
                rA[i][0] = *(const float2*)(A + (size_t)row0 * K + c0);
                rA[i][1] = *(const float2*)(A + (size_t)(row0 + 8) * K + c0);
                rA[i][2] = *(const float2*)(A + (size_t)row0 * K + c0 + 8);
                rA[i][3] = *(const float2*)(A + (size_t)(row0 + 8) * K + c0 + 8);
            }
            #pragma unroll
            for (int j = 0; j < 4; j++) {
                const int n = n0 + (warp + 8 * (j & 1)) * 8 + gid;
                const int k0 = kb + (j >> 1) * 16 + tig * 2;
                rB[j][0] = *(const float2*)(Bt + (size_t)n * K + k0);
                rB[j][1] = *(const float2*)(Bt + (size_t)n * K + k0 + 8);
            }
        }

        #pragma unroll
        for (int kk = 0; kk < 2; kk++) {
            uint4 ah[2], al[2];
            #pragma unroll
            for (int mf = 0; mf < 2; mf++) {
                int slot = kk * 8 + wm * 2 + mf;
                ah[mf] = Ah4[slot * 32 + lane];
                al[mf] = Al4[slot * 32 + lane];
            }
            #pragma unroll
            for (int nf = 0; nf < 8; nf++) {
                int slot = kk * 16 + wn * 8 + nf;
                uint2 bh = Bh2[slot * 32 + lane];
                uint2 bl = Bl2[slot * 32 + lane];
                #pragma unroll
                for (int mf = 0; mf < 2; mf++) {
                    MMA_F16(acc[mf][nf], ah[mf], bh);
                    MMA_F16(acc[mf][nf], ah[mf], bl);
                    MMA_F16(acc[mf][nf], al[mf], bh);
                }
            }
        }
        __syncthreads();
    }

    #pragma unroll
    for (int mf = 0; mf < 2; mf++) {
        const int r0 = m0 + wm * 32 + mf * 16 + gid;
        #pragma unroll
        for (int nf = 0; nf < 8; nf++) {
            const int c = n0 + wn * 64 + nf * 8 + tig * 2;
            float2 v0, v1;
            v0.x = acc[mf][nf][0]; v0.y = acc[mf][nf][1];
            v1.x = acc[mf][nf][2]; v1.y = acc[mf][nf][3];
            *(float2*)(C + (size_t)r0 * N + c) = v0;
            *(float2*)(C + (size_t)(r0 + 8) * N + c) = v1;
        }
    }
}

// ---------------- prep: Q fragments (fp16 hi/lo) ------------------------------
__global__ void qfrag_prep_kernel() {
    int t = blockIdx.x * 256 + threadIdx.x;     // 524288 total
    int lane = t & 31, kk = (t >> 5) & 7, rg = (t >> 8) & 127, h = t >> 15;
    int gid = lane >> 2, tig = lane & 3;
    int row0 = rg * 16 + gid;
    int c0 = h * DHEAD + kk * 16 + tig * 2;
    float2 a0 = *(const float2*)&g_qkv[(size_t)row0 * QKVN + c0];
    float2 a1 = *(const float2*)&g_qkv[(size_t)(row0 + 8) * QKVN + c0];
    float2 a2 = *(const float2*)&g_qkv[(size_t)row0 * QKVN + c0 + 8];
    float2 a3 = *(const float2*)&g_qkv[(size_t)(row0 + 8) * QKVN + c0 + 8];
    uint4 hv, lv;
    cvt_h2(a0.x, a0.y, hv.x, lv.x);
    cvt_h2(a1.x, a1.y, hv.y, lv.y);
    cvt_h2(a2.x, a2.y, hv.z, lv.z);
    cvt_h2(a3.x, a3.y, hv.w, lv.w);
    g_qh4[t] = hv;
    g_ql4[t] = lv;
}

// ---------------- prep: K transposed half2 planes ------------------------------
__global__ void kprep_kernel() {
    int t = blockIdx.x * 256 + threadIdx.x;     // 131072
    int j = t & 2047, d2 = t >> 11;
    float k0 = g_qkv[(size_t)j * QKVN + DIMM + 2 * d2];
    float k1 = g_qkv[(size_t)j * QKVN + DIMM + 2 * d2 + 1];
    unsigned h, l;
    cvt_h2(k0, k1, h, l);
    g_kt2h[d2 * SEQ + j] = h;
    g_kt2l[d2 * SEQ + j] = l;
}

// ---------------- prep: V j-paired half2 planes ---------------------------------
__global__ void vprep_kernel() {
    int t = blockIdx.x * 256 + threadIdx.x;     // 131072
    int d = t & 127, j2 = t >> 7;
    float v0 = g_qkv[(size_t)(2 * j2) * QKVN + DIMM + DHEAD + d];
    float v1 = g_qkv[(size_t)(2 * j2 + 1) * QKVN + DIMM + DHEAD + d];
    unsigned h, l;
    cvt_h2(v0, v1, h, l);
    g_vt2h[j2 * DHEAD + d] = h;
    g_vt2l[j2 * DHEAD + d] = l;
}

// ---------------- V suffix sums ------------------------------------------------
__global__ void vpart_kernel() {
    int blk = blockIdx.x, d = threadIdx.x;
    float s = 0.f;
    #pragma unroll 8
    for (int r = 0; r < 128; r++)
        s += g_qkv[(size_t)(blk * 128 + r) * QKVN + DIMM + DHEAD + d];
    g_vpart[blk * DHEAD + d] = s;
}
__global__ void vsuf_kernel() {
    int blk = blockIdx.x, d = threadIdx.x;
    float acc = 0.f;
    for (int b = blk + 1; b < 16; b++) acc += g_vpart[b * DHEAD + d];
    #pragma unroll 4
    for (int r = 127; r >= 0; r--) {
        int row = blk * 128 + r;
        g_vsuf[(size_t)row * DHEAD + d] = acc;
        acc += g_qkv[(size_t)row * QKVN + DIMM + DHEAD + d];
    }
}

// ---------------- fp16x3 tensor-core flash attention ----------------------------
// smem words: Kt2h[64][72]@0, Kt2l@4608, Vt2h[32][136]@9216, Vt2l@13568,
// Ph2[64][36]@17920, Pl2@20224, srmax@22528, srsum@22656. total 22784 w = 91136 B
__global__ __launch_bounds__(256) void attn_mma_kernel(const float* __restrict__ pos_bias) {
    extern __shared__ float sm[];
    unsigned* Ku = (unsigned*)sm;
    unsigned* Kl = (unsigned*)(sm + 4608);
    unsigned* Vu = (unsigned*)(sm + 9216);
    unsigned* Vl = (unsigned*)(sm + 13568);
    unsigned* Pu = (unsigned*)(sm + 17920);
    unsigned* Pl = (unsigned*)(sm + 20224);
    float* srmax = sm + 22528;
    float* srsum = sm + 22656;

    const int h  = blockIdx.y;
    const int ib = gridDim.x - 1 - blockIdx.x;
    const int i0 = ib * 64;
    const int tid = threadIdx.x, lane = tid & 31, warp = tid >> 5;
    const int wm = warp >> 1, wn = warp & 1;
    const int gid = lane >> 2, tig = lane & 3;

    const int rg = (i0 >> 4) + wm;
    const size_t qbase = ((size_t)(h * 128 + rg) * 8) * 32 + lane;

    const int jl = tid & 63, cb = tid >> 6;
    const int r0g = i0 + wm * 16 + gid, r1g = r0g + 8;
    const int rl0 = wm * 16 + gid;

    float o[8][4];
    #pragma unroll
    for (int nf = 0; nf < 8; nf++)
        #pragma unroll
        for (int q = 0; q < 4; q++) o[nf][q] = 0.f;
    float m0 = -1e30f, m1 = -1e30f, l0 = 0.f, l1 = 0.f;

    for (int jb = 0; jb <= ib; jb++) {
        const int j0 = jb * 64;
        __syncthreads();
        // K tile: Kt2[d2][j] stride 72
        #pragma unroll
        for (int it = 0; it < 16; it++) {
            int d2 = cb * 16 + it;
            Ku[d2 * 72 + jl] = g_kt2h[d2 * SEQ + j0 + jl];
            Kl[d2 * 72 + jl] = g_kt2l[d2 * SEQ + j0 + jl];
        }
        // V tile: Vt2[j2][d] stride 136
        #pragma unroll
        for (int it = 0; it < 16; it++) {
            int idx = it * 256 + tid;
            int j2 = idx >> 7, d = idx & 127;
            Vu[j2 * 136 + d] = g_vt2h[(j0 / 2 + j2) * DHEAD + d];
            Vl[j2 * 136 + d] = g_vt2l[(j0 / 2 + j2) * DHEAD + d];
        }
        __syncthreads();

        // ---- S = Q K^T (fp16 x3)
        float s[4][4];
        #pragma unroll
        for (int nf = 0; nf < 4; nf++)
            #pragma unroll
            for (int q = 0; q < 4; q++) s[nf][q] = 0.f;

        #pragma unroll
        for (int kk = 0; kk < 8; kk++) {
            uint4 qh = g_qh4[qbase + kk * 32];
            uint4 ql = g_ql4[qbase + kk * 32];
            const int kr0 = (kk * 8 + tig) * 72, kr1 = kr0 + 4 * 72;
            #pragma unroll
            for (int nf = 0; nf < 4; nf++) {
                int col = wn * 32 + nf * 8 + gid;
                uint2 bh = make_uint2(Ku[kr0 + col], Ku[kr1 + col]);
                uint2 bl = make_uint2(Kl[kr0 + col], Kl[kr1 + col]);
                MMA_F16(s[nf], qh, bh);
                MMA_F16(s[nf], qh, bl);
                MMA_F16(s[nf], ql, bh);
            }
        }

        // ---- + pos_bias, causal mask (diagonal block only)
        const float* pb0 = pos_bias + ((size_t)h * SEQ + r0g) * SEQ + j0 + wn * 32 + tig * 2;
        const float* pb1 = pb0 + (size_t)8 * SEQ;
        #pragma unroll
        for (int nf = 0; nf < 4; nf++) {
            float2 b0 = *(const float2*)(pb0 + nf * 8);
            float2 b1 = *(const float2*)(pb1 + nf * 8);
            s[nf][0] += b0.x; s[nf][1] += b0.y;
            s[nf][2] += b1.x; s[nf][3] += b1.y;
        }
        if (jb == ib) {
            #pragma unroll
            for (int nf = 0; nf < 4; nf++) {
                int c = j0 + wn * 32 + nf * 8 + tig * 2;
                if (c > r0g)     s[nf][0] = -1e30f;
                if (c + 1 > r0g) s[nf][1] = -1e30f;
                if (c > r1g)     s[nf][2] = -1e30f;
                if (c + 1 > r1g) s[nf][3] = -1e30f;
            }
        }

        // ---- row max
        float rm0 = -1e30f, rm1 = -1e30f;
        #pragma unroll
        for (int nf = 0; nf < 4; nf++) {
            rm0 = fmaxf(rm0, fmaxf(s[nf][0], s[nf][1]));
            rm1 = fmaxf(rm1, fmaxf(s[nf][2], s[nf][3]));
        }
        rm0 = fmaxf(rm0, __shfl_xor_sync(0xffffffffu, rm0, 1));
        rm0 = fmaxf(rm0, __shfl_xor_sync(0xffffffffu, rm0, 2));
        rm1 = fmaxf(rm1, __shfl_xor_sync(0xffffffffu, rm1, 1));
        rm1 = fmaxf(rm1, __shfl_xor_sync(0xffffffffu, rm1, 2));
        srmax[wn * 64 + rl0] = rm0;
        srmax[wn * 64 + rl0 + 8] = rm1;
        __syncthreads();
        float bm0 = fmaxf(srmax[rl0], srmax[64 + rl0]);
        float bm1 = fmaxf(srmax[rl0 + 8], srmax[64 + rl0 + 8]);
        float mn0 = fmaxf(m0, bm0), mn1 = fmaxf(m1, bm1);
        float sc0 = __expf(m0 - mn0), sc1 = __expf(m1 - mn1);

        // ---- exp + P staging (half2 hi/lo, stride 36) + row sum
        float rs0 = 0.f, rs1 = 0.f;
        #pragma unroll
        for (int nf = 0; nf < 4; nf++) {
            int pcol = wn * 16 + nf * 4 + tig;
            float p00 = __expf(s[nf][0] - mn0);
            float p01 = __expf(s[nf][1] - mn0);
            float p10 = __expf(s[nf][2] - mn1);
            float p11 = __expf(s[nf][3] - mn1);
            rs0 += p00 + p01; rs1 += p10 + p11;
            unsigned hw, lw;
            cvt_h2(p00, p01, hw, lw);
            Pu[rl0 * 36 + pcol] = hw; Pl[rl0 * 36 + pcol] = lw;
            cvt_h2(p10, p11, hw, lw);
            Pu[(rl0 + 8) * 36 + pcol] = hw; Pl[(rl0 + 8) * 36 + pcol] = lw;
        }
        rs0 += __shfl_xor_sync(0xffffffffu, rs0, 1);
        rs0 += __shfl_xor_sync(0xffffffffu, rs0, 2);
        rs1 += __shfl_xor_sync(0xffffffffu, rs1, 1);
        rs1 += __shfl_xor_sync(0xffffffffu, rs1, 2);
        srsum[wn * 64 + rl0] = rs0;
        srsum[wn * 64 + rl0 + 8] = rs1;
        __syncthreads();
        l0 = l0 * sc0 + srsum[rl0] + srsum[64 + rl0];
        l1 = l1 * sc1 + srsum[rl0 + 8] + srsum[64 + rl0 + 8];
        m0 = mn0; m1 = mn1;

        // ---- rescale O, then O += P V (fp16 x3)
        #pragma unroll
        for (int nf = 0; nf < 8; nf++) {
            o[nf][0] *= sc0; o[nf][1] *= sc0;
            o[nf][2] *= sc1; o[nf][3] *= sc1;
        }
        #pragma unroll
        for (int c = 0; c < 4; c++) {
            uint4 ah = make_uint4(Pu[rl0 * 36 + c * 8 + tig],
                                  Pu[(rl0 + 8) * 36 + c * 8 + tig],
                                  Pu[rl0 * 36 + c * 8 + 4 + tig],
                                  Pu[(rl0 + 8) * 36 + c * 8 + 4 + tig]);
            uint4 al = make_uint4(Pl[rl0 * 36 + c * 8 + tig],
                                  Pl[(rl0 + 8) * 36 + c * 8 + tig],
                                  Pl[rl0 * 36 + c * 8 + 4 + tig],
                                  Pl[(rl0 + 8) * 36 + c * 8 + 4 + tig]);
            const int vr0 = (c * 8 + tig) * 136, vr1 = vr0 + 4 * 136;
            #pragma unroll
            for (int nf = 0; nf < 8; nf++) {
                int dcol = wn * 64 + nf * 8 + gid;
                uint2 bh = make_uint2(Vu[vr0 + dcol], Vu[vr1 + dcol]);
                uint2 bl = make_uint2(Vl[vr0 + dcol], Vl[vr1 + dcol]);
                MMA_F16(o[nf], ah, bh);
                MMA_F16(o[nf], ah, bl);
                MMA_F16(o[nf], al, bh);
            }
        }
    }

    // ---- finalize with analytic MASK_VALUE tail
    float cnt0 = (float)(SEQ - 1 - r0g), cnt1 = (float)(SEQ - 1 - r1g);
    float mf0 = fmaxf(m0, MASKVF), mf1 = fmaxf(m1, MASKVF);
    float wu0 = __expf(m0 - mf0),  wu1 = __expf(m1 - mf1);
    float wk0 = __expf(MASKVF - mf0), wk1 = __expf(MASKVF - mf1);
    float iZ0 = 1.f / (l0 * wu0 + cnt0 * wk0);
    float iZ1 = 1.f / (l1 * wu1 + cnt1 * wk1);
    #pragma unroll
    for (int nf = 0; nf < 8; nf++) {
        int dcol = wn * 64 + nf * 8 + tig * 2;
        float2 vs0 = *(const float2*)&g_vsuf[(size_t)r0g * DHEAD + dcol];
        float2 vs1 = *(const float2*)&g_vsuf[(size_t)r1g * DHEAD + dcol];
        float2 out0, out1;
        out0.x = (o[nf][0] * wu0 + wk0 * vs0.x) * iZ0;
        out0.y = (o[nf][1] * wu0 + wk0 * vs0.y) * iZ0;
        out1.x = (o[nf][2] * wu1 + wk1 * vs1.x) * iZ1;
        out1.y = (o[nf][3] * wu1 + wk1 * vs1.y) * iZ1;
        *(float2*)&g_ao[(size_t)r0g * DIMM + h * DHEAD + dcol] = out0;
        *(float2*)&g_ao[(size_t)r1g * DIMM + h * DHEAD + dcol] = out1;
    }
}

// ---------------- launch ---------------------------------------------------------
extern "C" void kernel_launch(void* const* d_in, const int* in_sizes, int n_in,
                              void* d_out, int out_size) {
    (void)in_sizes; (void)n_in; (void)out_size;
    const float* x        = (const float*)d_in[0];
    const float* pos_bias = (const float*)d_in[1];
    const float* gamma    = (const float*)d_in[2];
    const float* wq       = (const float*)d_in[3];
    const float* wk       = (const float*)d_in[4];
    const float* wv       = (const float*)d_in[5];
    const float* wo       = (const float*)d_in[6];
    float* out = (float*)d_out;

    float *xn_p, *wcatT_p, *woT_p, *qkv_p, *ao_p;
    cudaGetSymbolAddress((void**)&xn_p,    g_xn);
    cudaGetSymbolAddress((void**)&wcatT_p, g_wcatT);
    cudaGetSymbolAddress((void**)&woT_p,   g_woT);
    cudaGetSymbolAddress((void**)&qkv_p,   g_qkv);
    cudaGetSymbolAddress((void**)&ao_p,    g_ao);

    const int MMA_SMEM  = 2 * 8192 * 4;      // 65536
    const int ATTN_SMEM = 22784 * 4;         // 91136
    cudaFuncSetAttribute(mma_gemm_kernel, cudaFuncAttributeMaxDynamicSharedMemorySize, MMA_SMEM);
    cudaFuncSetAttribute(attn_mma_kernel, cudaFuncAttributeMaxDynamicSharedMemorySize, ATTN_SMEM);

    dim3 tb(32, 8);
    transpose_kernel<<<dim3(DIMM / 32, DIMM / 32), tb>>>(wq, wcatT_p, DIMM, DIMM, SCALEF);
    transpose_kernel<<<dim3(DHEAD / 32, DIMM / 32), tb>>>(wk, wcatT_p + (size_t)2048 * DIMM, DIMM, DHEAD, 1.0f);
    transpose_kernel<<<dim3(DHEAD / 32, DIMM / 32), tb>>>(wv, wcatT_p + (size_t)2176 * DIMM, DIMM, DHEAD, 1.0f);
    transpose_kernel<<<dim3(DIMM / 32, DIMM / 32), tb>>>(wo, woT_p, DIMM, DIMM, 1.0f);

    rmsnorm_kernel<<<SEQ, 256>>>(x, gamma);

    mma_gemm_kernel<<<dim3(QKVN / 128, SEQ / 128), 256, MMA_SMEM>>>(
        xn_p, wcatT_p, qkv_p, SEQ, QKVN, DIMM);

    qfrag_prep_kernel<<<2048, 256>>>();
    kprep_kernel<<<512, 256>>>();
    vprep_kernel<<<512, 256>>>();
    vpart_kernel<<<16, 128>>>();
    vsuf_kernel<<<16, 128>>>();

    attn_mma_kernel<<<dim3(32, HEADS), 256, ATTN_SMEM>>>(pos_bias);

    mma_gemm_kernel<<<dim3(DIMM / 128, SEQ / 128), 256, MMA_SMEM>>>(
        ao_p, woT_p, out, SEQ, DIMM, DIMM);
}